// round 1
// baseline (speedup 1.0000x reference)
#include <cuda_runtime.h>
#include <cstdint>

#define B_ 8
#define S_ 2048
#define D_ 1024
#define E_ 8
#define F_ 2048
#define C_ 320
#define NTOK (B_*S_)

// ---------------- scratch (static device globals; no runtime allocation) ----------------
__device__ float g_norm[(size_t)NTOK * D_];          // 64 MB: RMSNorm output
__device__ float g_H[(size_t)B_ * E_ * C_ * F_];     // 160 MB: hidden activations
__device__ float g_maxp[NTOK];
__device__ int   g_eidx[NTOK];
__device__ int   g_kept[NTOK];
__device__ int   g_slot_tok[B_ * E_ * C_];
__device__ int   g_counts[B_ * E_];

__device__ __forceinline__ float gelu_new(float x) {
    const float c = 0.7978845608028654f;  // sqrt(2/pi)
    float x3 = x * x * x;
    return 0.5f * x * (1.0f + tanhf(c * (x + 0.044715f * x3)));
}

// ---------------- Kernel A: RMSNorm + gate logits + softmax-max + argmax ----------------
__global__ void __launch_bounds__(256) k_norm_gate(
        const float* __restrict__ data, const float* __restrict__ gate_w,
        const float* __restrict__ rms_w, float* __restrict__ out_logits) {
    int t = blockIdx.x;
    int tid = threadIdx.x;
    int lane = tid & 31, wid = tid >> 5;
    const float* row = data + (size_t)t * D_;

    float v[4];
    float ss = 0.f;
#pragma unroll
    for (int j = 0; j < 4; j++) { v[j] = row[tid + j * 256]; ss += v[j] * v[j]; }
#pragma unroll
    for (int o = 16; o; o >>= 1) ss += __shfl_down_sync(0xffffffffu, ss, o);

    __shared__ float s_w[8];
    __shared__ float s_scale;
    if (lane == 0) s_w[wid] = ss;
    __syncthreads();
    if (tid == 0) {
        float tot = 0.f;
#pragma unroll
        for (int w = 0; w < 8; w++) tot += s_w[w];
        s_scale = rsqrtf(tot * (1.0f / D_) + 1e-6f);
    }
    __syncthreads();
    float scale = s_scale;

    float acc[E_];
#pragma unroll
    for (int e = 0; e < E_; e++) acc[e] = 0.f;
    float* nrow = g_norm + (size_t)t * D_;
#pragma unroll
    for (int j = 0; j < 4; j++) {
        int d = tid + j * 256;
        float nv = v[j] * scale * rms_w[d];
        nrow[d] = nv;
        const float* gw = gate_w + (size_t)d * E_;
#pragma unroll
        for (int e = 0; e < E_; e++) acc[e] = fmaf(nv, gw[e], acc[e]);
    }
#pragma unroll
    for (int e = 0; e < E_; e++) {
#pragma unroll
        for (int o = 16; o; o >>= 1) acc[e] += __shfl_down_sync(0xffffffffu, acc[e], o);
    }
    __shared__ float s_log[8 * E_];
    if (lane == 0) {
#pragma unroll
        for (int e = 0; e < E_; e++) s_log[wid * E_ + e] = acc[e];
    }
    __syncthreads();
    __shared__ float s_logit[E_];
    if (tid < E_) {
        float l = 0.f;
#pragma unroll
        for (int w = 0; w < 8; w++) l += s_log[w * E_ + tid];
        s_logit[tid] = l;
        if (out_logits) out_logits[(size_t)t * E_ + tid] = l;
    }
    __syncthreads();
    if (tid == 0) {
        float mx = s_logit[0]; int mi = 0;
#pragma unroll
        for (int e = 1; e < E_; e++) { if (s_logit[e] > mx) { mx = s_logit[e]; mi = e; } }
        float se = 0.f;
#pragma unroll
        for (int e = 0; e < E_; e++) se += expf(s_logit[e] - mx);
        g_maxp[t] = 1.0f / se;       // max(softmax) = 1 / sum(exp(l - lmax))
        g_eidx[t] = mi;
    }
}

// ---------------- Kernel B: routing scan (cumsum over S per batch via warp ballot) ------
__global__ void k_route(float* __restrict__ out_idx) {
    int b = blockIdx.x;
    int lane = threadIdx.x;
    int counts[E_];
#pragma unroll
    for (int e = 0; e < E_; e++) counts[e] = 0;
    unsigned ltmask = (1u << lane) - 1u;
    for (int s0 = 0; s0 < S_; s0 += 32) {
        int s = s0 + lane;
        int t = b * S_ + s;
        int e = g_eidx[t];
        int pos = 0;
#pragma unroll
        for (int ee = 0; ee < E_; ee++) {
            unsigned m = __ballot_sync(0xffffffffu, e == ee);
            if (e == ee) pos = counts[ee] + __popc(m & ltmask);
            counts[ee] += __popc(m);
        }
        int kept = (pos < C_) ? 1 : 0;
        g_kept[t] = kept;
        if (kept) g_slot_tok[(b * E_ + e) * C_ + pos] = s;
        if (out_idx) out_idx[t] = kept ? (float)e : 0.0f;  // argmax of masked one-hot
    }
    if (lane < E_) {
        int c = counts[lane];
        g_counts[b * E_ + lane] = (c < C_) ? c : C_;
    }
}

// ---------------- Kernel C: GEMM1 (gather-A) + gelu -> H --------------------------------
// per (b,e): H[c, f] = gelu( sum_k norm[b, tok(c), k] * w1[e, k, f] )
__global__ void __launch_bounds__(256) k_ffn1(const float* __restrict__ w1) {
    int be = blockIdx.z;
    int b = be >> 3, e = be & 7;
    int count = g_counts[be];
    int m0 = blockIdx.y * 64;
    if (m0 >= count) return;
    int n0 = blockIdx.x * 64;

    __shared__ int   s_tok[64];
    __shared__ float As[16][64];
    __shared__ float Bs[16][64];
    int tid = threadIdx.x;
    if (tid < 64) {
        int c = m0 + tid;
        s_tok[tid] = (c < count) ? g_slot_tok[be * C_ + c] : 0;
    }
    __syncthreads();

    int am = tid >> 2;          // row within tile 0..63
    int ak = (tid & 3) * 4;     // k sub-offset 0,4,8,12
    const float* a_base = g_norm + ((size_t)b * S_ + s_tok[am]) * D_ + ak;
    int bk = tid >> 4;          // 0..15
    int bn = (tid & 15) * 4;
    const float* b_base = w1 + (size_t)e * D_ * F_ + (size_t)bk * F_ + n0 + bn;

    int tx = tid & 15, ty = tid >> 4;
    float acc[4][4];
#pragma unroll
    for (int i = 0; i < 4; i++)
#pragma unroll
        for (int j = 0; j < 4; j++) acc[i][j] = 0.f;

    for (int k0 = 0; k0 < D_; k0 += 16) {
        float4 av = *(const float4*)(a_base + k0);
        As[ak + 0][am] = av.x; As[ak + 1][am] = av.y;
        As[ak + 2][am] = av.z; As[ak + 3][am] = av.w;
        float4 bv = *(const float4*)(b_base + (size_t)k0 * F_);
        *(float4*)&Bs[bk][bn] = bv;
        __syncthreads();
#pragma unroll
        for (int k = 0; k < 16; k++) {
            float4 a  = *(const float4*)&As[k][ty * 4];
            float4 bb = *(const float4*)&Bs[k][tx * 4];
            float ar[4] = {a.x, a.y, a.z, a.w};
            float br[4] = {bb.x, bb.y, bb.z, bb.w};
#pragma unroll
            for (int i = 0; i < 4; i++)
#pragma unroll
                for (int j = 0; j < 4; j++) acc[i][j] = fmaf(ar[i], br[j], acc[i][j]);
        }
        __syncthreads();
    }
    float* Hbase = g_H + (size_t)be * C_ * F_;
#pragma unroll
    for (int i = 0; i < 4; i++) {
        int c = m0 + ty * 4 + i;
        if (c < count) {
            float* hp = Hbase + (size_t)c * F_ + n0 + tx * 4;
#pragma unroll
            for (int j = 0; j < 4; j++) hp[j] = gelu_new(acc[i][j]);
        }
    }
}

// ---------------- Kernel D: GEMM2 + combine scatter (final = data + maxp * y) ----------
__global__ void __launch_bounds__(256) k_ffn2(const float* __restrict__ w2,
        const float* __restrict__ data, float* __restrict__ out_final) {
    int be = blockIdx.z;
    int b = be >> 3, e = be & 7;
    int count = g_counts[be];
    int m0 = blockIdx.y * 64;
    if (m0 >= count) return;
    int n0 = blockIdx.x * 64;

    __shared__ int   s_tok[64];
    __shared__ float As[16][64];
    __shared__ float Bs[16][64];
    int tid = threadIdx.x;
    if (tid < 64) {
        int c = m0 + tid;
        s_tok[tid] = (c < count) ? g_slot_tok[be * C_ + c] : 0;
    }
    __syncthreads();

    int am = tid >> 2;
    int ak = (tid & 3) * 4;
    const float* a_base = g_H + ((size_t)be * C_ + m0 + am) * F_ + ak;
    int bk = tid >> 4;
    int bn = (tid & 15) * 4;
    const float* b_base = w2 + (size_t)e * F_ * D_ + (size_t)bk * D_ + n0 + bn;

    int tx = tid & 15, ty = tid >> 4;
    float acc[4][4];
#pragma unroll
    for (int i = 0; i < 4; i++)
#pragma unroll
        for (int j = 0; j < 4; j++) acc[i][j] = 0.f;

    for (int k0 = 0; k0 < F_; k0 += 16) {
        float4 av = *(const float4*)(a_base + k0);
        As[ak + 0][am] = av.x; As[ak + 1][am] = av.y;
        As[ak + 2][am] = av.z; As[ak + 3][am] = av.w;
        float4 bv = *(const float4*)(b_base + (size_t)k0 * D_);
        *(float4*)&Bs[bk][bn] = bv;
        __syncthreads();
#pragma unroll
        for (int k = 0; k < 16; k++) {
            float4 a  = *(const float4*)&As[k][ty * 4];
            float4 bb = *(const float4*)&Bs[k][tx * 4];
            float ar[4] = {a.x, a.y, a.z, a.w};
            float br[4] = {bb.x, bb.y, bb.z, bb.w};
#pragma unroll
            for (int i = 0; i < 4; i++)
#pragma unroll
                for (int j = 0; j < 4; j++) acc[i][j] = fmaf(ar[i], br[j], acc[i][j]);
        }
        __syncthreads();
    }
#pragma unroll
    for (int i = 0; i < 4; i++) {
        int c = m0 + ty * 4 + i;
        if (c < count) {
            int s = s_tok[ty * 4 + i];
            int t = b * S_ + s;
            float mp = g_maxp[t];
            const float* dp = data + (size_t)t * D_ + n0 + tx * 4;
            float* op = out_final + (size_t)t * D_ + n0 + tx * 4;
#pragma unroll
            for (int j = 0; j < 4; j++) op[j] = dp[j] + mp * acc[i][j];
        }
    }
}

// ---------------- Kernel E: dropped tokens keep norm (clone semantics) ------------------
__global__ void k_dropped(const float* __restrict__ data, float* __restrict__ out_final) {
    int t = blockIdx.x;
    if (g_kept[t]) return;
    float mp = g_maxp[t];
    int tid = threadIdx.x;
    const float* dp = data + (size_t)t * D_;
    const float* np = g_norm + (size_t)t * D_;
    float* op = out_final + (size_t)t * D_;
    for (int j = tid; j < D_; j += blockDim.x)
        op[j] = dp[j] + mp * np[j];
}

// ---------------- launch ---------------------------------------------------------------
extern "C" void kernel_launch(void* const* d_in, const int* in_sizes, int n_in,
                              void* d_out, int out_size) {
    const float* data   = (const float*)d_in[0];
    const float* gate_w = (const float*)d_in[1];
    const float* w1     = (const float*)d_in[2];
    const float* w2     = (const float*)d_in[3];
    const float* rms_w  = (const float*)d_in[4];
    float* out = (float*)d_out;

    const size_t FIN = (size_t)NTOK * D_;
    const size_t LG  = (size_t)NTOK * E_;
    const size_t IX  = (size_t)NTOK;
    float* out_logits = ((size_t)out_size >= FIN + LG)      ? out + FIN      : nullptr;
    float* out_idx    = ((size_t)out_size >= FIN + LG + IX) ? out + FIN + LG : nullptr;

    k_norm_gate<<<NTOK, 256>>>(data, gate_w, rms_w, out_logits);
    k_route<<<B_, 32>>>(out_idx);
    dim3 g1(F_ / 64, C_ / 64, B_ * E_);   // 32 x 5 x 64
    k_ffn1<<<g1, 256>>>(w1);
    dim3 g2(D_ / 64, C_ / 64, B_ * E_);   // 16 x 5 x 64
    k_ffn2<<<g2, 256>>>(w2, data, out);
    k_dropped<<<NTOK, 128>>>(data, out);
}

// round 16
// speedup vs baseline: 2.3012x; 2.3012x over previous
#include <cuda_runtime.h>
#include <cstdint>

#define B_ 8
#define S_ 2048
#define D_ 1024
#define E_ 8
#define F_ 2048
#define C_ 320
#define NTOK (B_*S_)
#define CH 32                 // k per chunk
#define MP 36                 // padded row stride in floats (144B = 9*16B)
#define TILE_F (128*MP)       // floats per tile (A or B)
#define SMEM_DYN (512 + 2*2*TILE_F*4)   // s_tok + 2 buffers x (A+B)

// ---------------- scratch ----------------
__device__ float g_norm[(size_t)NTOK * D_];          // tf32-rounded norm
__device__ float g_H[(size_t)B_ * E_ * C_ * F_];     // tf32-rounded hidden
__device__ float g_W1t[(size_t)E_ * F_ * D_];        // [e][f][k] tf32-rounded
__device__ float g_W2t[(size_t)E_ * D_ * F_];        // [e][d][f] tf32-rounded
__device__ float g_maxp[NTOK];
__device__ int   g_eidx[NTOK];
__device__ int   g_kept[NTOK];
__device__ int   g_slot_tok[B_ * E_ * C_];
__device__ int   g_counts[B_ * E_];

// ---------------- helpers ----------------
__device__ __forceinline__ uint32_t smem_u32(const void* p) {
    uint32_t a;
    asm("{ .reg .u64 t; cvta.to.shared.u64 t, %1; cvt.u32.u64 %0, t; }" : "=r"(a) : "l"(p));
    return a;
}
__device__ __forceinline__ uint32_t tf32u(float x) {
    uint32_t u;
    asm("cvt.rna.tf32.f32 %0, %1;" : "=r"(u) : "f"(x));
    return u;
}
__device__ __forceinline__ void cp16(uint32_t s, const void* g) {
    asm volatile("cp.async.cg.shared.global [%0], [%1], 16;" :: "r"(s), "l"(g));
}
#define CP_COMMIT() asm volatile("cp.async.commit_group;" ::: "memory")

__device__ __forceinline__ void mma8(float* c, const uint32_t* a, const uint32_t* b) {
    asm volatile(
        "mma.sync.aligned.m16n8k8.row.col.f32.tf32.tf32.f32 "
        "{%0,%1,%2,%3}, {%4,%5,%6,%7}, {%8,%9}, {%0,%1,%2,%3};"
        : "+f"(c[0]), "+f"(c[1]), "+f"(c[2]), "+f"(c[3])
        : "r"(a[0]), "r"(a[1]), "r"(a[2]), "r"(a[3]), "r"(b[0]), "r"(b[1]));
}

__device__ __forceinline__ float gelu_new(float x) {
    const float c = 0.7978845608028654f;
    float x3 = x * x * x;
    return 0.5f * x * (1.0f + tanhf(c * (x + 0.044715f * x3)));
}

// ---------------- Kernel A: RMSNorm + gate logits + max-prob + argmax ----------------
__global__ void __launch_bounds__(256) k_norm_gate(
        const float* __restrict__ data, const float* __restrict__ gate_w,
        const float* __restrict__ rms_w, float* __restrict__ out_logits) {
    int t = blockIdx.x;
    int tid = threadIdx.x;
    int lane = tid & 31, wid = tid >> 5;
    const float* row = data + (size_t)t * D_;

    float v[4];
    float ss = 0.f;
#pragma unroll
    for (int j = 0; j < 4; j++) { v[j] = row[tid + j * 256]; ss += v[j] * v[j]; }
#pragma unroll
    for (int o = 16; o; o >>= 1) ss += __shfl_down_sync(0xffffffffu, ss, o);

    __shared__ float s_w[8];
    __shared__ float s_scale;
    if (lane == 0) s_w[wid] = ss;
    __syncthreads();
    if (tid == 0) {
        float tot = 0.f;
#pragma unroll
        for (int w = 0; w < 8; w++) tot += s_w[w];
        s_scale = rsqrtf(tot * (1.0f / D_) + 1e-6f);
    }
    __syncthreads();
    float scale = s_scale;

    float acc[E_];
#pragma unroll
    for (int e = 0; e < E_; e++) acc[e] = 0.f;
    float* nrow = g_norm + (size_t)t * D_;
#pragma unroll
    for (int j = 0; j < 4; j++) {
        int d = tid + j * 256;
        float nv = v[j] * scale * rms_w[d];
        nrow[d] = __uint_as_float(tf32u(nv));   // store tf32-rounded for MMA feed
        const float* gw = gate_w + (size_t)d * E_;
#pragma unroll
        for (int e = 0; e < E_; e++) acc[e] = fmaf(nv, gw[e], acc[e]);
    }
#pragma unroll
    for (int e = 0; e < E_; e++) {
#pragma unroll
        for (int o = 16; o; o >>= 1) acc[e] += __shfl_down_sync(0xffffffffu, acc[e], o);
    }
    __shared__ float s_log[8 * E_];
    if (lane == 0) {
#pragma unroll
        for (int e = 0; e < E_; e++) s_log[wid * E_ + e] = acc[e];
    }
    __syncthreads();
    __shared__ float s_logit[E_];
    if (tid < E_) {
        float l = 0.f;
#pragma unroll
        for (int w = 0; w < 8; w++) l += s_log[w * E_ + tid];
        s_logit[tid] = l;
        if (out_logits) out_logits[(size_t)t * E_ + tid] = l;
    }
    __syncthreads();
    if (tid == 0) {
        float mx = s_logit[0]; int mi = 0;
#pragma unroll
        for (int e = 1; e < E_; e++) { if (s_logit[e] > mx) { mx = s_logit[e]; mi = e; } }
        float se = 0.f;
#pragma unroll
        for (int e = 0; e < E_; e++) se += expf(s_logit[e] - mx);
        g_maxp[t] = 1.0f / se;
        g_eidx[t] = mi;
    }
}

// ---------------- Kernel B: routing scan ----------------
__global__ void k_route(float* __restrict__ out_idx) {
    int b = blockIdx.x;
    int lane = threadIdx.x;
    int counts[E_];
#pragma unroll
    for (int e = 0; e < E_; e++) counts[e] = 0;
    unsigned ltmask = (1u << lane) - 1u;
    for (int s0 = 0; s0 < S_; s0 += 32) {
        int s = s0 + lane;
        int t = b * S_ + s;
        int e = g_eidx[t];
        int pos = 0;
#pragma unroll
        for (int ee = 0; ee < E_; ee++) {
            unsigned m = __ballot_sync(0xffffffffu, e == ee);
            if (e == ee) pos = counts[ee] + __popc(m & ltmask);
            counts[ee] += __popc(m);
        }
        int kept = (pos < C_) ? 1 : 0;
        g_kept[t] = kept;
        if (kept) g_slot_tok[(b * E_ + e) * C_ + pos] = s;
        if (out_idx) out_idx[t] = kept ? (float)e : 0.0f;
    }
    if (lane < E_) {
        int c = counts[lane];
        g_counts[b * E_ + lane] = (c < C_) ? c : C_;
    }
}

// ---------------- transpose + round-to-tf32: src [E][R][Cc] -> dst [E][Cc][R] ----------
__global__ void __launch_bounds__(256) k_transpose(const float* __restrict__ src,
                                                   float* __restrict__ dst, int R, int Cc) {
    __shared__ float tbuf[32][33];
    int e = blockIdx.z;
    int r0 = blockIdx.y * 32, c0 = blockIdx.x * 32;
    int tx = threadIdx.x, ty = threadIdx.y;   // 32 x 8
    const float* s = src + (size_t)e * R * Cc;
    float* d = dst + (size_t)e * R * Cc;
#pragma unroll
    for (int i = 0; i < 32; i += 8)
        tbuf[ty + i][tx] = s[(size_t)(r0 + ty + i) * Cc + c0 + tx];
    __syncthreads();
#pragma unroll
    for (int i = 0; i < 32; i += 8)
        d[(size_t)(c0 + ty + i) * R + r0 + tx] = __uint_as_float(tf32u(tbuf[tx][ty + i]));
}

// ---------------- GEMM1: mma.sync tf32; H = gelu(gather(norm) @ w1) -------------------
__global__ void __launch_bounds__(256, 2) k_ffn1_mma(const float* __restrict__ w1t) {
    extern __shared__ float sm[];
    int tid = threadIdx.x, l = tid & 31, wid = tid >> 5;
    int be = blockIdx.z, b = be >> 3, e = be & 7;
    int count = g_counts[be];
    int m0 = blockIdx.y * 128;
    if (m0 >= count) return;
    int n0 = blockIdx.x * 128;

    int* s_tok = (int*)sm;
    float* tiles = sm + 128;
    uint32_t tiles_u = smem_u32(tiles);

    if (tid < 128) {
        int c = m0 + tid;
        s_tok[tid] = (c < count) ? g_slot_tok[be * C_ + c] : g_slot_tok[be * C_];
    }
    __syncthreads();

    int r = tid >> 1, q = tid & 1;
    const float* a_row = g_norm + ((size_t)b * S_ + s_tok[r]) * D_ + q * 16;
    const float* b_row = w1t + ((size_t)e * F_ + n0 + r) * D_ + q * 16;
    uint32_t dA = tiles_u + (r * MP + q * 16) * 4;
    uint32_t dB = dA + TILE_F * 4;

    auto load_chunk = [&](int c) {
        uint32_t off = (c & 1) * 2 * TILE_F * 4;
        const float* ga = a_row + c * CH;
        const float* gb = b_row + c * CH;
#pragma unroll
        for (int j = 0; j < 4; j++) cp16(dA + off + j * 16, ga + j * 4);
#pragma unroll
        for (int j = 0; j < 4; j++) cp16(dB + off + j * 16, gb + j * 4);
        CP_COMMIT();
    };

    int wm = (wid & 3) * 32, wn = (wid >> 2) * 64;
    float acc[2][8][4];
#pragma unroll
    for (int mt = 0; mt < 2; mt++)
#pragma unroll
        for (int nt = 0; nt < 8; nt++)
#pragma unroll
            for (int j = 0; j < 4; j++) acc[mt][nt][j] = 0.f;

    const int NCH = D_ / CH;
    load_chunk(0);
    for (int c = 0; c < NCH; c++) {
        if (c + 1 < NCH) { load_chunk(c + 1); asm volatile("cp.async.wait_group 1;" ::: "memory"); }
        else             { asm volatile("cp.async.wait_group 0;" ::: "memory"); }
        __syncthreads();
        const float* A = tiles + (c & 1) * 2 * TILE_F;
        const float* Bt = A + TILE_F;
#pragma unroll
        for (int kk = 0; kk < CH; kk += 8) {
            uint32_t af[2][4], bf[8][2];
#pragma unroll
            for (int mt = 0; mt < 2; mt++) {
                int row = wm + mt * 16 + (l >> 2);
                af[mt][0] = __float_as_uint(A[row * MP + kk + (l & 3)]);
                af[mt][1] = __float_as_uint(A[(row + 8) * MP + kk + (l & 3)]);
                af[mt][2] = __float_as_uint(A[row * MP + kk + 4 + (l & 3)]);
                af[mt][3] = __float_as_uint(A[(row + 8) * MP + kk + 4 + (l & 3)]);
            }
#pragma unroll
            for (int nt = 0; nt < 8; nt++) {
                int col = wn + nt * 8 + (l >> 2);
                bf[nt][0] = __float_as_uint(Bt[col * MP + kk + (l & 3)]);
                bf[nt][1] = __float_as_uint(Bt[col * MP + kk + 4 + (l & 3)]);
            }
#pragma unroll
            for (int mt = 0; mt < 2; mt++)
#pragma unroll
                for (int nt = 0; nt < 8; nt++) mma8(acc[mt][nt], af[mt], bf[nt]);
        }
        __syncthreads();
    }

    // epilogue: gelu + round, store to g_H
#pragma unroll
    for (int mt = 0; mt < 2; mt++) {
        int ib = wm + mt * 16 + (l >> 2);
#pragma unroll
        for (int h = 0; h < 2; h++) {
            int c = m0 + ib + h * 8;
            if (c >= count) continue;
            float* hp = g_H + ((size_t)be * C_ + c) * F_ + n0 + wn + 2 * (l & 3);
#pragma unroll
            for (int nt = 0; nt < 8; nt++) {
                float2 o;
                o.x = __uint_as_float(tf32u(gelu_new(acc[mt][nt][h * 2 + 0])));
                o.y = __uint_as_float(tf32u(gelu_new(acc[mt][nt][h * 2 + 1])));
                *(float2*)(hp + nt * 8) = o;
            }
        }
    }
}

// ---------------- GEMM2: mma.sync tf32; final = data + maxp*(H @ w2), scatter ---------
__global__ void __launch_bounds__(256, 2) k_ffn2_mma(const float* __restrict__ w2t,
        const float* __restrict__ data, float* __restrict__ out_final) {
    extern __shared__ float sm[];
    int tid = threadIdx.x, l = tid & 31, wid = tid >> 5;
    int be = blockIdx.z, b = be >> 3, e = be & 7;
    int count = g_counts[be];
    int m0 = blockIdx.y * 128;
    if (m0 >= count) return;
    int n0 = blockIdx.x * 128;

    int* s_tok = (int*)sm;
    float* tiles = sm + 128;
    uint32_t tiles_u = smem_u32(tiles);

    if (tid < 128) {
        int c = m0 + tid;
        s_tok[tid] = (c < count) ? g_slot_tok[be * C_ + c] : g_slot_tok[be * C_];
    }
    __syncthreads();

    int r = tid >> 1, q = tid & 1;
    int cr = m0 + r; cr = (cr < count) ? cr : 0;
    const float* a_row = g_H + ((size_t)be * C_ + cr) * F_ + q * 16;
    const float* b_row = w2t + ((size_t)e * D_ + n0 + r) * F_ + q * 16;
    uint32_t dA = tiles_u + (r * MP + q * 16) * 4;
    uint32_t dB = dA + TILE_F * 4;

    auto load_chunk = [&](int c) {
        uint32_t off = (c & 1) * 2 * TILE_F * 4;
        const float* ga = a_row + c * CH;
        const float* gb = b_row + c * CH;
#pragma unroll
        for (int j = 0; j < 4; j++) cp16(dA + off + j * 16, ga + j * 4);
#pragma unroll
        for (int j = 0; j < 4; j++) cp16(dB + off + j * 16, gb + j * 4);
        CP_COMMIT();
    };

    int wm = (wid & 3) * 32, wn = (wid >> 2) * 64;
    float acc[2][8][4];
#pragma unroll
    for (int mt = 0; mt < 2; mt++)
#pragma unroll
        for (int nt = 0; nt < 8; nt++)
#pragma unroll
            for (int j = 0; j < 4; j++) acc[mt][nt][j] = 0.f;

    const int NCH = F_ / CH;
    load_chunk(0);
    for (int c = 0; c < NCH; c++) {
        if (c + 1 < NCH) { load_chunk(c + 1); asm volatile("cp.async.wait_group 1;" ::: "memory"); }
        else             { asm volatile("cp.async.wait_group 0;" ::: "memory"); }
        __syncthreads();
        const float* A = tiles + (c & 1) * 2 * TILE_F;
        const float* Bt = A + TILE_F;
#pragma unroll
        for (int kk = 0; kk < CH; kk += 8) {
            uint32_t af[2][4], bf[8][2];
#pragma unroll
            for (int mt = 0; mt < 2; mt++) {
                int row = wm + mt * 16 + (l >> 2);
                af[mt][0] = __float_as_uint(A[row * MP + kk + (l & 3)]);
                af[mt][1] = __float_as_uint(A[(row + 8) * MP + kk + (l & 3)]);
                af[mt][2] = __float_as_uint(A[row * MP + kk + 4 + (l & 3)]);
                af[mt][3] = __float_as_uint(A[(row + 8) * MP + kk + 4 + (l & 3)]);
            }
#pragma unroll
            for (int nt = 0; nt < 8; nt++) {
                int col = wn + nt * 8 + (l >> 2);
                bf[nt][0] = __float_as_uint(Bt[col * MP + kk + (l & 3)]);
                bf[nt][1] = __float_as_uint(Bt[col * MP + kk + 4 + (l & 3)]);
            }
#pragma unroll
            for (int mt = 0; mt < 2; mt++)
#pragma unroll
                for (int nt = 0; nt < 8; nt++) mma8(acc[mt][nt], af[mt], bf[nt]);
        }
        __syncthreads();
    }

    // epilogue: final = data + maxp * acc, scattered to token rows
#pragma unroll
    for (int mt = 0; mt < 2; mt++) {
        int ib = wm + mt * 16 + (l >> 2);
#pragma unroll
        for (int h = 0; h < 2; h++) {
            int c = m0 + ib + h * 8;
            if (c >= count) continue;
            int t = b * S_ + s_tok[ib + h * 8];
            float mp = g_maxp[t];
            const float* dp = data + (size_t)t * D_ + n0 + wn + 2 * (l & 3);
            float* op = out_final + (size_t)t * D_ + n0 + wn + 2 * (l & 3);
#pragma unroll
            for (int nt = 0; nt < 8; nt++) {
                float2 d4 = *(const float2*)(dp + nt * 8);
                float2 o;
                o.x = d4.x + mp * acc[mt][nt][h * 2 + 0];
                o.y = d4.y + mp * acc[mt][nt][h * 2 + 1];
                *(float2*)(op + nt * 8) = o;
            }
        }
    }
}

// ---------------- dropped tokens ----------------
__global__ void k_dropped(const float* __restrict__ data, float* __restrict__ out_final) {
    int t = blockIdx.x;
    if (g_kept[t]) return;
    float mp = g_maxp[t];
    int tid = threadIdx.x;
    const float* dp = data + (size_t)t * D_;
    const float* np = g_norm + (size_t)t * D_;
    float* op = out_final + (size_t)t * D_;
    for (int j = tid; j < D_; j += blockDim.x)
        op[j] = dp[j] + mp * np[j];
}

// ---------------- launch ----------------
extern "C" void kernel_launch(void* const* d_in, const int* in_sizes, int n_in,
                              void* d_out, int out_size) {
    const float* data   = (const float*)d_in[0];
    const float* gate_w = (const float*)d_in[1];
    const float* w1     = (const float*)d_in[2];
    const float* w2     = (const float*)d_in[3];
    const float* rms_w  = (const float*)d_in[4];
    float* out = (float*)d_out;

    const size_t FIN = (size_t)NTOK * D_;
    const size_t LG  = (size_t)NTOK * E_;
    const size_t IX  = (size_t)NTOK;
    float* out_logits = ((size_t)out_size >= FIN + LG)      ? out + FIN      : nullptr;
    float* out_idx    = ((size_t)out_size >= FIN + LG + IX) ? out + FIN + LG : nullptr;

    cudaFuncSetAttribute(k_ffn1_mma, cudaFuncAttributeMaxDynamicSharedMemorySize, SMEM_DYN);
    cudaFuncSetAttribute(k_ffn2_mma, cudaFuncAttributeMaxDynamicSharedMemorySize, SMEM_DYN);

    float* w1t; cudaGetSymbolAddress((void**)&w1t, g_W1t);
    float* w2t; cudaGetSymbolAddress((void**)&w2t, g_W2t);

    k_norm_gate<<<NTOK, 256>>>(data, gate_w, rms_w, out_logits);
    k_route<<<B_, 32>>>(out_idx);
    k_transpose<<<dim3(F_ / 32, D_ / 32, E_), dim3(32, 8)>>>(w1, w1t, D_, F_);
    k_transpose<<<dim3(D_ / 32, F_ / 32, E_), dim3(32, 8)>>>(w2, w2t, F_, D_);
    k_ffn1_mma<<<dim3(F_ / 128, 3, B_ * E_), 256, SMEM_DYN>>>(w1t);
    k_ffn2_mma<<<dim3(D_ / 128, 3, B_ * E_), 256, SMEM_DYN>>>(w2t, data, out);
    k_dropped<<<NTOK, 128>>>(data, out);
}